// round 12
// baseline (speedup 1.0000x reference)
#include <cuda_runtime.h>
#include <cuda_fp16.h>
#include <cstdint>

#define N_NODES 100000
#define N_EDGES 6400000
#define F_IN    128
#define HID     16
#define SCAN_BLK 1024
#define NB_SCAN ((N_NODES + SCAN_BLK - 1) / SCAN_BLK)   // 98
#define SRC_MASK 0x1FFFFu
#define WQ_SCALE 32767.0f

// ---------------- scratch (static device globals; no runtime alloc) ----------
__device__ __align__(16) unsigned int g_csru[N_EDGES];  // [wq:15 | src:17], dst-grouped
__device__ unsigned long long g_degcnt[N_NODES];        // [cnt:22][deg fixed 2^-22:42]
__device__ int   g_off[N_NODES + 1];
__device__ int   g_cur[N_NODES];
__device__ float g_dis[N_NODES];
__device__ int   g_bsum[NB_SCAN];
__device__ __align__(32) __half g_yha[N_NODES * HID];   // message ping buffer (y*dis, fp16)
__device__ __align__(32) __half g_yhb[N_NODES * HID];   // message pong buffer
__device__ float g_y4h[N_NODES];                        // layer-4 prescaled message
__device__ int   g_is64;

// ---------------- preprocessing ----------------------------------------------

__global__ void k_detect(const long long* __restrict__ e64) {
    int is64 = 1;
#pragma unroll
    for (int i = 0; i < 16; i++) {
        long long v = e64[i];
        if (v < 0 || v >= N_NODES) { is64 = 0; break; }
    }
    g_is64 = is64;
}

__global__ void k_init_nodes() {
    int i = blockIdx.x * blockDim.x + threadIdx.x;
    if (i < N_NODES) g_degcnt[i] = (1ull << 22);   // deg = 1.0 (self-loop), cnt = 0
}

// reads ONLY the dst half of edges + w; one packed atomic; no scratch writes
__global__ void k_edge_pre(const void* __restrict__ edges,
                           const float* __restrict__ w) {
    int e = blockIdx.x * blockDim.x + threadIdx.x;
    if (e >= N_EDGES) return;
    int d;
    if (g_is64) d = (int)((const long long*)edges)[N_EDGES + e];
    else        d = ((const int*)edges)[N_EDGES + e];
    d = min(max(d, 0), N_NODES - 1);
    unsigned long long pack =
        (1ull << 42) | (unsigned long long)(w[e] * 4194304.0f);  // w * 2^22
    atomicAdd(&g_degcnt[d], pack);
}

// scan phase 1: per-block exclusive scan of counts; also compute dis
__global__ void k_scan1() {
    __shared__ int ws[32];
    int b = blockIdx.x, t = threadIdx.x;
    int i = b * SCAN_BLK + t;
    int lane = t & 31, wid = t >> 5;

    int v = 0;
    if (i < N_NODES) {
        unsigned long long dc = g_degcnt[i];
        v = (int)(dc >> 42);
        float deg = (float)(dc & ((1ull << 42) - 1)) * (1.0f / 4194304.0f);
        g_dis[i] = rsqrtf(deg);
    }
    int x = v;
#pragma unroll
    for (int o = 1; o < 32; o <<= 1) {
        int y = __shfl_up_sync(0xffffffffu, x, o);
        if (lane >= o) x += y;
    }
    if (lane == 31) ws[wid] = x;
    __syncthreads();
    if (wid == 0) {
        int s = ws[lane];
#pragma unroll
        for (int o = 1; o < 32; o <<= 1) {
            int y = __shfl_up_sync(0xffffffffu, s, o);
            if (lane >= o) s += y;
        }
        ws[lane] = s;
    }
    __syncthreads();
    int excl = x - v + (wid > 0 ? ws[wid - 1] : 0);
    if (i < N_NODES) g_off[i] = excl;
    if (t == SCAN_BLK - 1) g_bsum[b] = excl + v;
}

// scan phase 2: exclusive scan of NB_SCAN block totals
__global__ void k_scan2() {
    __shared__ int ws[4];
    int t = threadIdx.x;
    int lane = t & 31, wid = t >> 5;
    int v = (t < NB_SCAN) ? g_bsum[t] : 0;
    int x = v;
#pragma unroll
    for (int o = 1; o < 32; o <<= 1) {
        int y = __shfl_up_sync(0xffffffffu, x, o);
        if (lane >= o) x += y;
    }
    if (lane == 31) ws[wid] = x;
    __syncthreads();
    if (wid == 0 && lane < 4) {
        int s = ws[lane];
#pragma unroll
        for (int o = 1; o < 4; o <<= 1) {
            int y = __shfl_up_sync(0x0000000fu, s, o);
            if (lane >= o) s += y;
        }
        ws[lane] = s;
    }
    __syncthreads();
    int excl = x - v + (wid > 0 ? ws[wid - 1] : 0);
    if (t < NB_SCAN) g_bsum[t] = excl;
}

// scan phase 3: add block offsets; init cursors; finalize sentinel
__global__ void k_scan3() {
    int i = blockIdx.x * blockDim.x + threadIdx.x;
    if (i < N_NODES) {
        int o = g_off[i] + g_bsum[i / SCAN_BLK];
        g_off[i] = o;
        g_cur[i] = o;
    }
    if (i == 0) g_off[N_NODES] = N_EDGES;
}

// fill CSR: re-read edges, write ONE packed 4B entry per edge
__global__ void k_csr_fill(const void* __restrict__ edges,
                           const float* __restrict__ w) {
    int e = blockIdx.x * blockDim.x + threadIdx.x;
    if (e >= N_EDGES) return;
    int s, d;
    if (g_is64) {
        const long long* p = (const long long*)edges;
        s = (int)p[e];
        d = (int)p[N_EDGES + e];
    } else {
        const int* p = (const int*)edges;
        s = p[e];
        d = p[N_EDGES + e];
    }
    s = min(max(s, 0), N_NODES - 1);
    d = min(max(d, 0), N_NODES - 1);
    unsigned int wq = (unsigned int)(w[e] * WQ_SCALE + 0.5f);
    int pos = atomicAdd(&g_cur[d], 1);
    g_csru[pos] = (unsigned int)s | (wq << 17);
}

// ---------------- layer-1 dense transform -------------------------------------

// writes into g_yha
__global__ void k_t1(const float* __restrict__ x, const float* __restrict__ W1) {
    __shared__ float Ws[F_IN * HID];
    for (int t = threadIdx.x; t < F_IN * HID; t += blockDim.x) Ws[t] = W1[t];
    __syncthreads();

    int i = blockIdx.x * blockDim.x + threadIdx.x;
    if (i >= N_NODES) return;

    float acc[HID];
#pragma unroll
    for (int c = 0; c < HID; c++) acc[c] = 0.f;

    const float4* xr = reinterpret_cast<const float4*>(x + (size_t)i * F_IN);
#pragma unroll 8
    for (int k4 = 0; k4 < F_IN / 4; k4++) {
        float4 xv = __ldg(&xr[k4]);
        float xk[4] = {xv.x, xv.y, xv.z, xv.w};
#pragma unroll
        for (int j = 0; j < 4; j++) {
            const float4* wrow = reinterpret_cast<const float4*>(&Ws[(k4 * 4 + j) * HID]);
#pragma unroll
            for (int c4 = 0; c4 < 4; c4++) {
                float4 wv = wrow[c4];
                acc[c4*4+0] = fmaf(xk[j], wv.x, acc[c4*4+0]);
                acc[c4*4+1] = fmaf(xk[j], wv.y, acc[c4*4+1]);
                acc[c4*4+2] = fmaf(xk[j], wv.z, acc[c4*4+2]);
                acc[c4*4+3] = fmaf(xk[j], wv.w, acc[c4*4+3]);
            }
        }
    }
    float dis = g_dis[i];
    __half2 hp[8];
#pragma unroll
    for (int c = 0; c < 8; c++)
        hp[c] = __floats2half2_rn(acc[2*c] * dis, acc[2*c+1] * dis);
    uint4* yo = reinterpret_cast<uint4*>(g_yha + (size_t)i * HID);
    yo[0] = *reinterpret_cast<uint4*>(&hp[0]);
    yo[1] = *reinterpret_cast<uint4*>(&hp[4]);
}

// ---------------- fused pull + transform (no atomics) --------------------------

__device__ __forceinline__ void acc8(uint4 v, float wgt, float* acc) {
    float2 f;
    f = __half22float2(*reinterpret_cast<__half2*>(&v.x));
    acc[0] = fmaf(f.x, wgt, acc[0]); acc[1] = fmaf(f.y, wgt, acc[1]);
    f = __half22float2(*reinterpret_cast<__half2*>(&v.y));
    acc[2] = fmaf(f.x, wgt, acc[2]); acc[3] = fmaf(f.y, wgt, acc[3]);
    f = __half22float2(*reinterpret_cast<__half2*>(&v.z));
    acc[4] = fmaf(f.x, wgt, acc[4]); acc[5] = fmaf(f.y, wgt, acc[5]);
    f = __half22float2(*reinterpret_cast<__half2*>(&v.w));
    acc[6] = fmaf(f.x, wgt, acc[6]); acc[7] = fmaf(f.y, wgt, acc[7]);
}

// gather-reduce core: acc[8] = sum over in-edges of w_e * yh_in[src_e] (half li)
__device__ __forceinline__ void pull_core(const __half* __restrict__ yh_in,
                                          int gw, int grp, int li, float* acc) {
    int beg = g_off[gw], end = g_off[gw + 1];
    int e = beg + grp;
    for (; e + 16 < end; e += 32) {
        unsigned int c0 = __ldg(&g_csru[e]);
        unsigned int c1 = __ldg(&g_csru[e + 16]);
        int   s0 = (int)(c0 & SRC_MASK);
        int   s1 = (int)(c1 & SRC_MASK);
        float w0 = (float)(c0 >> 17) * (1.0f / WQ_SCALE);
        float w1 = (float)(c1 >> 17) * (1.0f / WQ_SCALE);
        uint4 v0 = __ldg(reinterpret_cast<const uint4*>(yh_in + (size_t)s0 * HID) + li);
        uint4 v1 = __ldg(reinterpret_cast<const uint4*>(yh_in + (size_t)s1 * HID) + li);
        acc8(v0, w0, acc);
        acc8(v1, w1, acc);
    }
    if (e < end) {
        unsigned int c = __ldg(&g_csru[e]);
        int   s = (int)(c & SRC_MASK);
        float wv = (float)(c >> 17) * (1.0f / WQ_SCALE);
        uint4 v = __ldg(reinterpret_cast<const uint4*>(yh_in + (size_t)s * HID) + li);
        acc8(v, wv, acc);
    }
#pragma unroll
    for (int m = 2; m <= 16; m <<= 1)
#pragma unroll
        for (int c = 0; c < 8; c++)
            acc[c] += __shfl_xor_sync(0xffffffffu, acc[c], m);
}

// mid layers: agg = dis*(pull + self); a = relu(agg + bprev); y = a@W;
// yh_out = y*dis.  ab selects direction: 1 = A->B, 0 = B->A (ping-pong).
__global__ void k_pull_mid(int ab,
                           const float* __restrict__ W,
                           const float* __restrict__ bprev) {
    const __half* yh_in  = ab ? g_yha : g_yhb;
    __half*       yh_out = ab ? g_yhb : g_yha;

    __shared__ float Ws[HID * HID];
    __shared__ float bs[HID];
    for (int t = threadIdx.x; t < HID * HID; t += blockDim.x) Ws[t] = W[t];
    if (threadIdx.x < HID) bs[threadIdx.x] = bprev[threadIdx.x];
    __syncthreads();

    int gw = (blockIdx.x * blockDim.x + threadIdx.x) >> 5;
    if (gw >= N_NODES) return;
    int lane = threadIdx.x & 31;
    int grp  = lane >> 1;
    int li   = lane & 1;

    float acc[8];
#pragma unroll
    for (int c = 0; c < 8; c++) acc[c] = 0.f;
    pull_core(yh_in, gw, grp, li, acc);

    if (lane < 2) {
        float dis = g_dis[gw];
        uint4 vs = __ldg(reinterpret_cast<const uint4*>(yh_in + (size_t)gw * HID) + li);
        acc8(vs, 1.0f, acc);

        float a[8];
#pragma unroll
        for (int c = 0; c < 8; c++)
            a[c] = fmaxf(fmaf(acc[c], dis, bs[li * 8 + c]), 0.f);

        float ao[8];
#pragma unroll
        for (int c = 0; c < 8; c++)
            ao[c] = __shfl_xor_sync(0x3u, a[c], 1);

        float afull[HID];
#pragma unroll
        for (int c = 0; c < 8; c++) {
            afull[li * 8 + c]       = a[c];
            afull[(1 - li) * 8 + c] = ao[c];
        }

        float y[8];
#pragma unroll
        for (int c = 0; c < 8; c++) y[c] = 0.f;
#pragma unroll
        for (int k = 0; k < HID; k++) {
            float ak = afull[k];
            const float* wrow = &Ws[k * HID + li * 8];
#pragma unroll
            for (int c = 0; c < 8; c++)
                y[c] = fmaf(ak, wrow[c], y[c]);
        }

        __half2 hp[4];
#pragma unroll
        for (int c = 0; c < 4; c++)
            hp[c] = __floats2half2_rn(y[2*c] * dis, y[2*c+1] * dis);
        reinterpret_cast<uint4*>(yh_out + (size_t)gw * HID)[li] =
            *reinterpret_cast<uint4*>(&hp[0]);
    }
}

// last 16-wide layer (reads A): y4h = (relu(dis*(pull+self) + b3) . W4) * dis
__global__ void k_pull_last(const float* __restrict__ W4,
                            const float* __restrict__ b3) {
    const __half* yh_in = g_yha;

    __shared__ float W4s[HID];
    __shared__ float bs[HID];
    if (threadIdx.x < HID) { W4s[threadIdx.x] = W4[threadIdx.x]; bs[threadIdx.x] = b3[threadIdx.x]; }
    __syncthreads();

    int gw = (blockIdx.x * blockDim.x + threadIdx.x) >> 5;
    if (gw >= N_NODES) return;
    int lane = threadIdx.x & 31;
    int grp  = lane >> 1;
    int li   = lane & 1;

    float acc[8];
#pragma unroll
    for (int c = 0; c < 8; c++) acc[c] = 0.f;
    pull_core(yh_in, gw, grp, li, acc);

    if (lane < 2) {
        float dis = g_dis[gw];
        uint4 vs = __ldg(reinterpret_cast<const uint4*>(yh_in + (size_t)gw * HID) + li);
        acc8(vs, 1.0f, acc);

        float part = 0.f;
#pragma unroll
        for (int c = 0; c < 8; c++) {
            float a = fmaxf(fmaf(acc[c], dis, bs[li * 8 + c]), 0.f);
            part = fmaf(a, W4s[li * 8 + c], part);
        }
        part += __shfl_xor_sync(0x3u, part, 1);
        if (lane == 0) g_y4h[gw] = part * dis;
    }
}

// layer-4 pull + fused global mean pool
__global__ void k_pull1(const float* __restrict__ b4, float* __restrict__ out) {
    int gw = (blockIdx.x * blockDim.x + threadIdx.x) >> 5;
    int lane = threadIdx.x & 31;
    int wid = threadIdx.x >> 5;
    __shared__ float sbuf[8];

    float v = 0.f;
    if (gw < N_NODES) {
        int beg = g_off[gw], end = g_off[gw + 1];
        float acc = 0.f;
        for (int e = beg + lane; e < end; e += 32) {
            unsigned int c = __ldg(&g_csru[e]);
            acc = fmaf(__ldg(&g_y4h[c & SRC_MASK]),
                       (float)(c >> 17) * (1.0f / WQ_SCALE), acc);
        }
#pragma unroll
        for (int o = 16; o > 0; o >>= 1)
            acc += __shfl_xor_sync(0xffffffffu, acc, o);
        float agg4 = (acc + g_y4h[gw]) * g_dis[gw];
        v = fmaxf(agg4 + b4[0], 0.f) * (1.0f / (float)N_NODES);
    }
    if (lane == 0) sbuf[wid] = v;
    __syncthreads();
    if (wid == 0) {
        v = (lane < (int)(blockDim.x >> 5)) ? sbuf[lane] : 0.f;
#pragma unroll
        for (int o = 4; o > 0; o >>= 1) v += __shfl_down_sync(0xffffffffu, v, o);
        if (lane == 0) atomicAdd(out, v);
    }
}

__global__ void k_zero_out(float* out) { out[0] = 0.f; }

// ---------------- launch ------------------------------------------------------

extern "C" void kernel_launch(void* const* d_in, const int* in_sizes, int n_in,
                              void* d_out, int out_size) {
    const float* vf    = (const float*)d_in[0];
    const void*  edges = d_in[1];
    const float* w     = (const float*)d_in[2];
    const float* W1    = (const float*)d_in[3];
    const float* b1    = (const float*)d_in[4];
    const float* W2    = (const float*)d_in[5];
    const float* b2    = (const float*)d_in[6];
    const float* W3    = (const float*)d_in[7];
    const float* b3    = (const float*)d_in[8];
    const float* W4    = (const float*)d_in[9];
    const float* b4    = (const float*)d_in[10];
    float*       out   = (float*)d_out;

    const int NB_N = (N_NODES + 255) / 256;
    const int NB_E = (N_EDGES + 255) / 256;
    const int NB_W = (N_NODES * 32 + 255) / 256;   // warp-per-node grids

    // ---- CSR build ----
    k_detect<<<1, 1>>>((const long long*)edges);
    k_init_nodes<<<NB_N, 256>>>();
    k_edge_pre<<<NB_E, 256>>>(edges, w);
    k_scan1<<<NB_SCAN, SCAN_BLK>>>();
    k_scan2<<<1, 128>>>();
    k_scan3<<<NB_N, 256>>>();
    k_csr_fill<<<NB_E, 256>>>(edges, w);

    // ---- 4 GCN layers (fused pull + transform, ping-pong A/B) ----
    k_t1<<<NB_N, 256>>>(vf, W1);                 // -> A
    k_pull_mid<<<NB_W, 256>>>(1, W2, b1);        // A -> B
    k_pull_mid<<<NB_W, 256>>>(0, W3, b2);        // B -> A
    k_pull_last<<<NB_W, 256>>>(W4, b3);          // A -> y4h

    k_zero_out<<<1, 1>>>(out);
    k_pull1<<<NB_W, 256>>>(b4, out);
}

// round 14
// speedup vs baseline: 1.1223x; 1.1223x over previous
#include <cuda_runtime.h>
#include <cuda_fp16.h>
#include <cstdint>

#define N_NODES 100000
#define N_EDGES 6400000
#define F_IN    128
#define HID     16
#define SCAN_BLK 1024
#define NB_SCAN ((N_NODES + SCAN_BLK - 1) / SCAN_BLK)   // 98
#define SRC_MASK 0x1FFFFu
#define WQ_SCALE 32767.0f

// ---------------- scratch (static device globals; no runtime alloc) ----------
__device__ __align__(16) unsigned int g_csru[N_EDGES];  // [wq:15 | src:17], dst-grouped
__device__ unsigned long long g_degcnt[N_NODES];        // [cnt:22][deg fixed 2^-22:42]
__device__ int   g_off[N_NODES + 1];
__device__ int   g_cur[N_NODES];
__device__ float g_dis[N_NODES];
__device__ int   g_bsum[NB_SCAN];
__device__ __align__(32) __half g_yha[N_NODES * HID];   // message ping buffer (y*dis, fp16)
__device__ __align__(32) __half g_yhb[N_NODES * HID];   // message pong buffer
__device__ float g_y4h[N_NODES];                        // layer-4 prescaled message
__device__ int   g_is64;

// ---------------- preprocessing ----------------------------------------------

__global__ void k_detect(const long long* __restrict__ e64) {
    int is64 = 1;
#pragma unroll
    for (int i = 0; i < 16; i++) {
        long long v = e64[i];
        if (v < 0 || v >= N_NODES) { is64 = 0; break; }
    }
    g_is64 = is64;
}

__global__ void k_init_nodes() {
    int i = blockIdx.x * blockDim.x + threadIdx.x;
    if (i < N_NODES) g_degcnt[i] = (1ull << 22);   // deg = 1.0 (self-loop), cnt = 0
}

// reads ONLY the dst half of edges + w; one packed atomic; no scratch writes
__global__ void k_edge_pre(const void* __restrict__ edges,
                           const float* __restrict__ w) {
    int e = blockIdx.x * blockDim.x + threadIdx.x;
    if (e >= N_EDGES) return;
    int d;
    if (g_is64) d = (int)((const long long*)edges)[N_EDGES + e];
    else        d = ((const int*)edges)[N_EDGES + e];
    d = min(max(d, 0), N_NODES - 1);
    unsigned long long pack =
        (1ull << 42) | (unsigned long long)(w[e] * 4194304.0f);  // w * 2^22
    atomicAdd(&g_degcnt[d], pack);
}

// scan phase 1: per-block exclusive scan of counts; also compute dis
__global__ void k_scan1() {
    __shared__ int ws[32];
    int b = blockIdx.x, t = threadIdx.x;
    int i = b * SCAN_BLK + t;
    int lane = t & 31, wid = t >> 5;

    int v = 0;
    if (i < N_NODES) {
        unsigned long long dc = g_degcnt[i];
        v = (int)(dc >> 42);
        float deg = (float)(dc & ((1ull << 42) - 1)) * (1.0f / 4194304.0f);
        g_dis[i] = rsqrtf(deg);
    }
    int x = v;
#pragma unroll
    for (int o = 1; o < 32; o <<= 1) {
        int y = __shfl_up_sync(0xffffffffu, x, o);
        if (lane >= o) x += y;
    }
    if (lane == 31) ws[wid] = x;
    __syncthreads();
    if (wid == 0) {
        int s = ws[lane];
#pragma unroll
        for (int o = 1; o < 32; o <<= 1) {
            int y = __shfl_up_sync(0xffffffffu, s, o);
            if (lane >= o) s += y;
        }
        ws[lane] = s;
    }
    __syncthreads();
    int excl = x - v + (wid > 0 ? ws[wid - 1] : 0);
    if (i < N_NODES) g_off[i] = excl;
    if (t == SCAN_BLK - 1) g_bsum[b] = excl + v;
}

// scan phase 2: exclusive scan of NB_SCAN block totals
__global__ void k_scan2() {
    __shared__ int ws[4];
    int t = threadIdx.x;
    int lane = t & 31, wid = t >> 5;
    int v = (t < NB_SCAN) ? g_bsum[t] : 0;
    int x = v;
#pragma unroll
    for (int o = 1; o < 32; o <<= 1) {
        int y = __shfl_up_sync(0xffffffffu, x, o);
        if (lane >= o) x += y;
    }
    if (lane == 31) ws[wid] = x;
    __syncthreads();
    if (wid == 0 && lane < 4) {
        int s = ws[lane];
#pragma unroll
        for (int o = 1; o < 4; o <<= 1) {
            int y = __shfl_up_sync(0x0000000fu, s, o);
            if (lane >= o) s += y;
        }
        ws[lane] = s;
    }
    __syncthreads();
    int excl = x - v + (wid > 0 ? ws[wid - 1] : 0);
    if (t < NB_SCAN) g_bsum[t] = excl;
}

// scan phase 3: add block offsets; init cursors; finalize sentinel
__global__ void k_scan3() {
    int i = blockIdx.x * blockDim.x + threadIdx.x;
    if (i < N_NODES) {
        int o = g_off[i] + g_bsum[i / SCAN_BLK];
        g_off[i] = o;
        g_cur[i] = o;
    }
    if (i == 0) g_off[N_NODES] = N_EDGES;
}

// fill CSR: re-read edges, write ONE packed 4B entry per edge
__global__ void k_csr_fill(const void* __restrict__ edges,
                           const float* __restrict__ w) {
    int e = blockIdx.x * blockDim.x + threadIdx.x;
    if (e >= N_EDGES) return;
    int s, d;
    if (g_is64) {
        const long long* p = (const long long*)edges;
        s = (int)p[e];
        d = (int)p[N_EDGES + e];
    } else {
        const int* p = (const int*)edges;
        s = p[e];
        d = p[N_EDGES + e];
    }
    s = min(max(s, 0), N_NODES - 1);
    d = min(max(d, 0), N_NODES - 1);
    unsigned int wq = (unsigned int)(w[e] * WQ_SCALE + 0.5f);
    int pos = atomicAdd(&g_cur[d], 1);
    g_csru[pos] = (unsigned int)s | (wq << 17);
}

// ---------------- layer-1 dense transform -------------------------------------

// writes into g_yha
__global__ void k_t1(const float* __restrict__ x, const float* __restrict__ W1) {
    __shared__ float Ws[F_IN * HID];
    for (int t = threadIdx.x; t < F_IN * HID; t += blockDim.x) Ws[t] = W1[t];
    __syncthreads();

    int i = blockIdx.x * blockDim.x + threadIdx.x;
    if (i >= N_NODES) return;

    float acc[HID];
#pragma unroll
    for (int c = 0; c < HID; c++) acc[c] = 0.f;

    const float4* xr = reinterpret_cast<const float4*>(x + (size_t)i * F_IN);
#pragma unroll 8
    for (int k4 = 0; k4 < F_IN / 4; k4++) {
        float4 xv = __ldg(&xr[k4]);
        float xk[4] = {xv.x, xv.y, xv.z, xv.w};
#pragma unroll
        for (int j = 0; j < 4; j++) {
            const float4* wrow = reinterpret_cast<const float4*>(&Ws[(k4 * 4 + j) * HID]);
#pragma unroll
            for (int c4 = 0; c4 < 4; c4++) {
                float4 wv = wrow[c4];
                acc[c4*4+0] = fmaf(xk[j], wv.x, acc[c4*4+0]);
                acc[c4*4+1] = fmaf(xk[j], wv.y, acc[c4*4+1]);
                acc[c4*4+2] = fmaf(xk[j], wv.z, acc[c4*4+2]);
                acc[c4*4+3] = fmaf(xk[j], wv.w, acc[c4*4+3]);
            }
        }
    }
    float dis = g_dis[i];
    __half2 hp[8];
#pragma unroll
    for (int c = 0; c < 8; c++)
        hp[c] = __floats2half2_rn(acc[2*c] * dis, acc[2*c+1] * dis);
    uint4* yo = reinterpret_cast<uint4*>(g_yha + (size_t)i * HID);
    yo[0] = *reinterpret_cast<uint4*>(&hp[0]);
    yo[1] = *reinterpret_cast<uint4*>(&hp[4]);
}

// ---------------- fused pull + transform (no atomics) --------------------------

__device__ __forceinline__ void acc8(uint4 v, float wgt, float* acc) {
    float2 f;
    f = __half22float2(*reinterpret_cast<__half2*>(&v.x));
    acc[0] = fmaf(f.x, wgt, acc[0]); acc[1] = fmaf(f.y, wgt, acc[1]);
    f = __half22float2(*reinterpret_cast<__half2*>(&v.y));
    acc[2] = fmaf(f.x, wgt, acc[2]); acc[3] = fmaf(f.y, wgt, acc[3]);
    f = __half22float2(*reinterpret_cast<__half2*>(&v.z));
    acc[4] = fmaf(f.x, wgt, acc[4]); acc[5] = fmaf(f.y, wgt, acc[5]);
    f = __half22float2(*reinterpret_cast<__half2*>(&v.w));
    acc[6] = fmaf(f.x, wgt, acc[6]); acc[7] = fmaf(f.y, wgt, acc[7]);
}

// gather-reduce core: after the xor-reduce, EVERY lane holds the reduced
// acc[8] for its feature half (li)
__device__ __forceinline__ void pull_core(const __half* __restrict__ yh_in,
                                          int gw, int grp, int li, float* acc) {
    int beg = g_off[gw], end = g_off[gw + 1];
    int e = beg + grp;
    for (; e + 16 < end; e += 32) {
        unsigned int c0 = __ldg(&g_csru[e]);
        unsigned int c1 = __ldg(&g_csru[e + 16]);
        int   s0 = (int)(c0 & SRC_MASK);
        int   s1 = (int)(c1 & SRC_MASK);
        float w0 = (float)(c0 >> 17) * (1.0f / WQ_SCALE);
        float w1 = (float)(c1 >> 17) * (1.0f / WQ_SCALE);
        uint4 v0 = __ldg(reinterpret_cast<const uint4*>(yh_in + (size_t)s0 * HID) + li);
        uint4 v1 = __ldg(reinterpret_cast<const uint4*>(yh_in + (size_t)s1 * HID) + li);
        acc8(v0, w0, acc);
        acc8(v1, w1, acc);
    }
    if (e < end) {
        unsigned int c = __ldg(&g_csru[e]);
        int   s = (int)(c & SRC_MASK);
        float wv = (float)(c >> 17) * (1.0f / WQ_SCALE);
        uint4 v = __ldg(reinterpret_cast<const uint4*>(yh_in + (size_t)s * HID) + li);
        acc8(v, wv, acc);
    }
#pragma unroll
    for (int m = 2; m <= 16; m <<= 1)
#pragma unroll
        for (int c = 0; c < 8; c++)
            acc[c] += __shfl_xor_sync(0xffffffffu, acc[c], m);
}

// mid layers: agg = dis*(pull + self); a = relu(agg + bprev); y = a@W;
// yh_out = y*dis.  Register-lean all-lane epilogue: lane j computes output
// column j via shfl broadcasts (no per-thread 16-float arrays).
__global__ void __launch_bounds__(256, 6)
k_pull_mid(int ab, const float* __restrict__ W, const float* __restrict__ bprev) {
    const __half* yh_in  = ab ? g_yha : g_yhb;
    __half*       yh_out = ab ? g_yhb : g_yha;

    __shared__ float Ws[HID * HID];
    __shared__ float bs[HID];
    for (int t = threadIdx.x; t < HID * HID; t += blockDim.x) Ws[t] = W[t];
    if (threadIdx.x < HID) bs[threadIdx.x] = bprev[threadIdx.x];
    __syncthreads();

    int gw = (blockIdx.x * blockDim.x + threadIdx.x) >> 5;
    if (gw >= N_NODES) return;
    int lane = threadIdx.x & 31;
    int grp  = lane >> 1;
    int li   = lane & 1;

    float acc[8];
#pragma unroll
    for (int c = 0; c < 8; c++) acc[c] = 0.f;
    pull_core(yh_in, gw, grp, li, acc);

    // all lanes: add self-loop, apply bias + relu in place
    float dis = g_dis[gw];
    uint4 vs = __ldg(reinterpret_cast<const uint4*>(yh_in + (size_t)gw * HID) + li);
    acc8(vs, 1.0f, acc);
#pragma unroll
    for (int c = 0; c < 8; c++)
        acc[c] = fmaxf(fmaf(acc[c], dis, bs[li * 8 + c]), 0.f);

    // broadcast matmul: lane j (cols mod 16) accumulates y_j
    int col = lane & (HID - 1);
    float y = 0.f;
#pragma unroll
    for (int k = 0; k < HID; k++) {
        float ak = __shfl_sync(0xffffffffu, acc[k & 7], k >> 3);
        y = fmaf(ak, Ws[k * HID + col], y);
    }
    if (lane < HID)
        yh_out[(size_t)gw * HID + lane] = __float2half(y * dis);
}

// last 16-wide layer (reads A): y4h = (relu(dis*(pull+self) + b3) . W4) * dis
__global__ void __launch_bounds__(256, 6)
k_pull_last(const float* __restrict__ W4, const float* __restrict__ b3) {
    const __half* yh_in = g_yha;

    __shared__ float W4s[HID];
    __shared__ float bs[HID];
    if (threadIdx.x < HID) { W4s[threadIdx.x] = W4[threadIdx.x]; bs[threadIdx.x] = b3[threadIdx.x]; }
    __syncthreads();

    int gw = (blockIdx.x * blockDim.x + threadIdx.x) >> 5;
    if (gw >= N_NODES) return;
    int lane = threadIdx.x & 31;
    int grp  = lane >> 1;
    int li   = lane & 1;

    float acc[8];
#pragma unroll
    for (int c = 0; c < 8; c++) acc[c] = 0.f;
    pull_core(yh_in, gw, grp, li, acc);

    // all lanes: self-loop + bias/relu + dot with W4 over own half
    float dis = g_dis[gw];
    uint4 vs = __ldg(reinterpret_cast<const uint4*>(yh_in + (size_t)gw * HID) + li);
    acc8(vs, 1.0f, acc);
    float part = 0.f;
#pragma unroll
    for (int c = 0; c < 8; c++) {
        float a = fmaxf(fmaf(acc[c], dis, bs[li * 8 + c]), 0.f);
        part = fmaf(a, W4s[li * 8 + c], part);
    }
    part += __shfl_xor_sync(0xffffffffu, part, 1);
    if (lane == 0) g_y4h[gw] = part * dis;
}

// layer-4 pull + fused global mean pool
__global__ void __launch_bounds__(256, 6)
k_pull1(const float* __restrict__ b4, float* __restrict__ out) {
    int gw = (blockIdx.x * blockDim.x + threadIdx.x) >> 5;
    int lane = threadIdx.x & 31;
    int wid = threadIdx.x >> 5;
    __shared__ float sbuf[8];

    float v = 0.f;
    if (gw < N_NODES) {
        int beg = g_off[gw], end = g_off[gw + 1];
        float acc = 0.f;
        for (int e = beg + lane; e < end; e += 32) {
            unsigned int c = __ldg(&g_csru[e]);
            acc = fmaf(__ldg(&g_y4h[c & SRC_MASK]),
                       (float)(c >> 17) * (1.0f / WQ_SCALE), acc);
        }
#pragma unroll
        for (int o = 16; o > 0; o >>= 1)
            acc += __shfl_xor_sync(0xffffffffu, acc, o);
        float agg4 = (acc + g_y4h[gw]) * g_dis[gw];
        v = fmaxf(agg4 + b4[0], 0.f) * (1.0f / (float)N_NODES);
    }
    if (lane == 0) sbuf[wid] = v;
    __syncthreads();
    if (wid == 0) {
        v = (lane < (int)(blockDim.x >> 5)) ? sbuf[lane] : 0.f;
#pragma unroll
        for (int o = 4; o > 0; o >>= 1) v += __shfl_down_sync(0xffffffffu, v, o);
        if (lane == 0) atomicAdd(out, v);
    }
}

__global__ void k_zero_out(float* out) { out[0] = 0.f; }

// ---------------- launch ------------------------------------------------------

extern "C" void kernel_launch(void* const* d_in, const int* in_sizes, int n_in,
                              void* d_out, int out_size) {
    const float* vf    = (const float*)d_in[0];
    const void*  edges = d_in[1];
    const float* w     = (const float*)d_in[2];
    const float* W1    = (const float*)d_in[3];
    const float* b1    = (const float*)d_in[4];
    const float* W2    = (const float*)d_in[5];
    const float* b2    = (const float*)d_in[6];
    const float* W3    = (const float*)d_in[7];
    const float* b3    = (const float*)d_in[8];
    const float* W4    = (const float*)d_in[9];
    const float* b4    = (const float*)d_in[10];
    float*       out   = (float*)d_out;

    const int NB_N = (N_NODES + 255) / 256;
    const int NB_E = (N_EDGES + 255) / 256;
    const int NB_W = (N_NODES * 32 + 255) / 256;   // warp-per-node grids

    // ---- CSR build ----
    k_detect<<<1, 1>>>((const long long*)edges);
    k_init_nodes<<<NB_N, 256>>>();
    k_edge_pre<<<NB_E, 256>>>(edges, w);
    k_scan1<<<NB_SCAN, SCAN_BLK>>>();
    k_scan2<<<1, 128>>>();
    k_scan3<<<NB_N, 256>>>();
    k_csr_fill<<<NB_E, 256>>>(edges, w);

    // ---- 4 GCN layers (fused pull + transform, ping-pong A/B) ----
    k_t1<<<NB_N, 256>>>(vf, W1);                 // -> A
    k_pull_mid<<<NB_W, 256>>>(1, W2, b1);        // A -> B
    k_pull_mid<<<NB_W, 256>>>(0, W3, b2);        // B -> A
    k_pull_last<<<NB_W, 256>>>(W4, b3);          // A -> y4h

    k_zero_out<<<1, 1>>>(out);
    k_pull1<<<NB_W, 256>>>(b4, out);
}

// round 17
// speedup vs baseline: 1.1791x; 1.0505x over previous
#include <cuda_runtime.h>
#include <cuda_fp16.h>
#include <cstdint>

#define N_NODES 100000
#define N_EDGES 6400000
#define F_IN    128
#define HID     16
#define SCAN_BLK 1024
#define NB_SCAN ((N_NODES + SCAN_BLK - 1) / SCAN_BLK)   // 98
#define SRC_MASK 0x1FFFFu
#define WQ_SCALE 32767.0f

// ---------------- scratch (static device globals; no runtime alloc) ----------
__device__ __align__(16) unsigned int g_csru[N_EDGES];  // [wq:15 | src:17], dst-grouped
__device__ __align__(16) unsigned int g_dr[N_EDGES];    // [rank:15 | dst:17]
__device__ unsigned long long g_degcnt[N_NODES];        // [cnt:22][deg fixed 2^-22:42]
__device__ int   g_off[N_NODES + 1];
__device__ float g_dis[N_NODES];
__device__ int   g_bsum[NB_SCAN];
__device__ __align__(32) __half g_yha[N_NODES * HID];   // message ping buffer (y*dis, fp16)
__device__ __align__(32) __half g_yhb[N_NODES * HID];   // message pong buffer
__device__ float g_y4h[N_NODES];                        // layer-4 prescaled message
__device__ int   g_is64;

// ---------------- preprocessing ----------------------------------------------

// init degree/count; thread 0 also detects edge dtype (int64 vs int32 downcast)
__global__ void k_init(const long long* __restrict__ e64) {
    int i = blockIdx.x * blockDim.x + threadIdx.x;
    if (i < N_NODES) g_degcnt[i] = (1ull << 22);   // deg = 1.0 (self-loop), cnt = 0
    if (i == 0) {
        int is64 = 1;
#pragma unroll
        for (int k = 0; k < 16; k++) {
            long long v = e64[k];
            if (v < 0 || v >= N_NODES) { is64 = 0; break; }
        }
        g_is64 = is64;
    }
}

// reads ONLY the dst half of edges + w; one packed atomic whose RETURN VALUE
// gives this edge's within-node rank -> stored for an atomic-free fill
__global__ void k_edge_pre(const void* __restrict__ edges,
                           const float* __restrict__ w) {
    int e = blockIdx.x * blockDim.x + threadIdx.x;
    if (e >= N_EDGES) return;
    int d;
    if (g_is64) d = (int)__ldcs(&((const long long*)edges)[N_EDGES + e]);
    else        d = __ldcs(&((const int*)edges)[N_EDGES + e]);
    d = min(max(d, 0), N_NODES - 1);
    unsigned long long pack =
        (1ull << 42) | (unsigned long long)(__ldcs(&w[e]) * 4194304.0f);  // w * 2^22
    unsigned long long old = atomicAdd(&g_degcnt[d], pack);
    unsigned int r = (unsigned int)(old >> 42);
    g_dr[e] = (unsigned int)d | (min(r, 0x7FFFu) << 17);
}

// scan phase 1: per-block exclusive scan of counts; also compute dis
__global__ void k_scan1() {
    __shared__ int ws[32];
    int b = blockIdx.x, t = threadIdx.x;
    int i = b * SCAN_BLK + t;
    int lane = t & 31, wid = t >> 5;

    int v = 0;
    if (i < N_NODES) {
        unsigned long long dc = g_degcnt[i];
        v = (int)(dc >> 42);
        float deg = (float)(dc & ((1ull << 42) - 1)) * (1.0f / 4194304.0f);
        g_dis[i] = rsqrtf(deg);
    }
    int x = v;
#pragma unroll
    for (int o = 1; o < 32; o <<= 1) {
        int y = __shfl_up_sync(0xffffffffu, x, o);
        if (lane >= o) x += y;
    }
    if (lane == 31) ws[wid] = x;
    __syncthreads();
    if (wid == 0) {
        int s = ws[lane];
#pragma unroll
        for (int o = 1; o < 32; o <<= 1) {
            int y = __shfl_up_sync(0xffffffffu, s, o);
            if (lane >= o) s += y;
        }
        ws[lane] = s;
    }
    __syncthreads();
    int excl = x - v + (wid > 0 ? ws[wid - 1] : 0);
    if (i < N_NODES) g_off[i] = excl;
    if (t == SCAN_BLK - 1) g_bsum[b] = excl + v;
}

// scan phase 2: exclusive scan of NB_SCAN block totals
__global__ void k_scan2() {
    __shared__ int ws[4];
    int t = threadIdx.x;
    int lane = t & 31, wid = t >> 5;
    int v = (t < NB_SCAN) ? g_bsum[t] : 0;
    int x = v;
#pragma unroll
    for (int o = 1; o < 32; o <<= 1) {
        int y = __shfl_up_sync(0xffffffffu, x, o);
        if (lane >= o) x += y;
    }
    if (lane == 31) ws[wid] = x;
    __syncthreads();
    if (wid == 0 && lane < 4) {
        int s = ws[lane];
#pragma unroll
        for (int o = 1; o < 4; o <<= 1) {
            int y = __shfl_up_sync(0x0000000fu, s, o);
            if (lane >= o) s += y;
        }
        ws[lane] = s;
    }
    __syncthreads();
    int excl = x - v + (wid > 0 ? ws[wid - 1] : 0);
    if (t < NB_SCAN) g_bsum[t] = excl;
}

// scan phase 3: add block offsets; finalize sentinel
__global__ void k_scan3() {
    int i = blockIdx.x * blockDim.x + threadIdx.x;
    if (i < N_NODES) g_off[i] += g_bsum[i / SCAN_BLK];
    if (i == 0) g_off[N_NODES] = N_EDGES;
}

// fill CSR: atomic-free. pos = off[dst] + rank (rank captured in edge_pre).
__global__ void k_csr_fill(const void* __restrict__ edges,
                           const float* __restrict__ w) {
    int e = blockIdx.x * blockDim.x + threadIdx.x;
    if (e >= N_EDGES) return;
    int s;
    if (g_is64) s = (int)__ldcs(&((const long long*)edges)[e]);
    else        s = __ldcs(&((const int*)edges)[e]);
    s = min(max(s, 0), N_NODES - 1);
    unsigned int dr = __ldcs(&g_dr[e]);
    int d          = (int)(dr & SRC_MASK);
    unsigned int r = dr >> 17;
    unsigned int wq = (unsigned int)(__ldcs(&w[e]) * WQ_SCALE + 0.5f);
    int pos = __ldg(&g_off[d]) + (int)r;
    g_csru[pos] = (unsigned int)s | (wq << 17);
}

// ---------------- layer-1 dense transform -------------------------------------

// writes into g_yha
__global__ void k_t1(const float* __restrict__ x, const float* __restrict__ W1) {
    __shared__ float Ws[F_IN * HID];
    for (int t = threadIdx.x; t < F_IN * HID; t += blockDim.x) Ws[t] = W1[t];
    __syncthreads();

    int i = blockIdx.x * blockDim.x + threadIdx.x;
    if (i >= N_NODES) return;

    float acc[HID];
#pragma unroll
    for (int c = 0; c < HID; c++) acc[c] = 0.f;

    const float4* xr = reinterpret_cast<const float4*>(x + (size_t)i * F_IN);
#pragma unroll 8
    for (int k4 = 0; k4 < F_IN / 4; k4++) {
        float4 xv = __ldcs(&xr[k4]);
        float xk[4] = {xv.x, xv.y, xv.z, xv.w};
#pragma unroll
        for (int j = 0; j < 4; j++) {
            const float4* wrow = reinterpret_cast<const float4*>(&Ws[(k4 * 4 + j) * HID]);
#pragma unroll
            for (int c4 = 0; c4 < 4; c4++) {
                float4 wv = wrow[c4];
                acc[c4*4+0] = fmaf(xk[j], wv.x, acc[c4*4+0]);
                acc[c4*4+1] = fmaf(xk[j], wv.y, acc[c4*4+1]);
                acc[c4*4+2] = fmaf(xk[j], wv.z, acc[c4*4+2]);
                acc[c4*4+3] = fmaf(xk[j], wv.w, acc[c4*4+3]);
            }
        }
    }
    float dis = g_dis[i];
    __half2 hp[8];
#pragma unroll
    for (int c = 0; c < 8; c++)
        hp[c] = __floats2half2_rn(acc[2*c] * dis, acc[2*c+1] * dis);
    uint4* yo = reinterpret_cast<uint4*>(g_yha + (size_t)i * HID);
    yo[0] = *reinterpret_cast<uint4*>(&hp[0]);
    yo[1] = *reinterpret_cast<uint4*>(&hp[4]);
}

// ---------------- fused pull + transform (no atomics) --------------------------

__device__ __forceinline__ void acc8(uint4 v, float wgt, float* acc) {
    float2 f;
    f = __half22float2(*reinterpret_cast<__half2*>(&v.x));
    acc[0] = fmaf(f.x, wgt, acc[0]); acc[1] = fmaf(f.y, wgt, acc[1]);
    f = __half22float2(*reinterpret_cast<__half2*>(&v.y));
    acc[2] = fmaf(f.x, wgt, acc[2]); acc[3] = fmaf(f.y, wgt, acc[3]);
    f = __half22float2(*reinterpret_cast<__half2*>(&v.z));
    acc[4] = fmaf(f.x, wgt, acc[4]); acc[5] = fmaf(f.y, wgt, acc[5]);
    f = __half22float2(*reinterpret_cast<__half2*>(&v.w));
    acc[6] = fmaf(f.x, wgt, acc[6]); acc[7] = fmaf(f.y, wgt, acc[7]);
}

// gather-reduce core: after the xor-reduce, EVERY lane holds the reduced
// acc[8] for its feature half (li)
__device__ __forceinline__ void pull_core(const __half* __restrict__ yh_in,
                                          int gw, int grp, int li, float* acc) {
    int beg = g_off[gw], end = g_off[gw + 1];
    int e = beg + grp;
    for (; e + 16 < end; e += 32) {
        unsigned int c0 = __ldg(&g_csru[e]);
        unsigned int c1 = __ldg(&g_csru[e + 16]);
        int   s0 = (int)(c0 & SRC_MASK);
        int   s1 = (int)(c1 & SRC_MASK);
        float w0 = (float)(c0 >> 17) * (1.0f / WQ_SCALE);
        float w1 = (float)(c1 >> 17) * (1.0f / WQ_SCALE);
        uint4 v0 = __ldg(reinterpret_cast<const uint4*>(yh_in + (size_t)s0 * HID) + li);
        uint4 v1 = __ldg(reinterpret_cast<const uint4*>(yh_in + (size_t)s1 * HID) + li);
        acc8(v0, w0, acc);
        acc8(v1, w1, acc);
    }
    if (e < end) {
        unsigned int c = __ldg(&g_csru[e]);
        int   s = (int)(c & SRC_MASK);
        float wv = (float)(c >> 17) * (1.0f / WQ_SCALE);
        uint4 v = __ldg(reinterpret_cast<const uint4*>(yh_in + (size_t)s * HID) + li);
        acc8(v, wv, acc);
    }
#pragma unroll
    for (int m = 2; m <= 16; m <<= 1)
#pragma unroll
        for (int c = 0; c < 8; c++)
            acc[c] += __shfl_xor_sync(0xffffffffu, acc[c], m);
}

// mid layers: agg = dis*(pull + self); a = relu(agg + bprev); y = a@W;
// yh_out = y*dis.  Register-lean all-lane epilogue via shfl broadcasts.
__global__ void __launch_bounds__(256, 6)
k_pull_mid(int ab, const float* __restrict__ W, const float* __restrict__ bprev) {
    const __half* yh_in  = ab ? g_yha : g_yhb;
    __half*       yh_out = ab ? g_yhb : g_yha;

    __shared__ float Ws[HID * HID];
    __shared__ float bs[HID];
    for (int t = threadIdx.x; t < HID * HID; t += blockDim.x) Ws[t] = W[t];
    if (threadIdx.x < HID) bs[threadIdx.x] = bprev[threadIdx.x];
    __syncthreads();

    int gw = (blockIdx.x * blockDim.x + threadIdx.x) >> 5;
    if (gw >= N_NODES) return;
    int lane = threadIdx.x & 31;
    int grp  = lane >> 1;
    int li   = lane & 1;

    float acc[8];
#pragma unroll
    for (int c = 0; c < 8; c++) acc[c] = 0.f;
    pull_core(yh_in, gw, grp, li, acc);

    // all lanes: add self-loop, apply bias + relu in place
    float dis = g_dis[gw];
    uint4 vs = __ldg(reinterpret_cast<const uint4*>(yh_in + (size_t)gw * HID) + li);
    acc8(vs, 1.0f, acc);
#pragma unroll
    for (int c = 0; c < 8; c++)
        acc[c] = fmaxf(fmaf(acc[c], dis, bs[li * 8 + c]), 0.f);

    // broadcast matmul: lane j (cols mod 16) accumulates y_j
    int col = lane & (HID - 1);
    float y = 0.f;
#pragma unroll
    for (int k = 0; k < HID; k++) {
        float ak = __shfl_sync(0xffffffffu, acc[k & 7], k >> 3);
        y = fmaf(ak, Ws[k * HID + col], y);
    }
    if (lane < HID)
        yh_out[(size_t)gw * HID + lane] = __float2half(y * dis);
}

// last 16-wide layer (reads A): y4h = (relu(dis*(pull+self) + b3) . W4) * dis
// block 0 thread 0 also zero-initializes out (safe: k_pull1 launches after)
__global__ void __launch_bounds__(256, 6)
k_pull_last(const float* __restrict__ W4, const float* __restrict__ b3,
            float* __restrict__ out) {
    if (blockIdx.x == 0 && threadIdx.x == 0) out[0] = 0.f;

    const __half* yh_in = g_yha;

    __shared__ float W4s[HID];
    __shared__ float bs[HID];
    if (threadIdx.x < HID) { W4s[threadIdx.x] = W4[threadIdx.x]; bs[threadIdx.x] = b3[threadIdx.x]; }
    __syncthreads();

    int gw = (blockIdx.x * blockDim.x + threadIdx.x) >> 5;
    if (gw >= N_NODES) return;
    int lane = threadIdx.x & 31;
    int grp  = lane >> 1;
    int li   = lane & 1;

    float acc[8];
#pragma unroll
    for (int c = 0; c < 8; c++) acc[c] = 0.f;
    pull_core(yh_in, gw, grp, li, acc);

    // all lanes: self-loop + bias/relu + dot with W4 over own half
    float dis = g_dis[gw];
    uint4 vs = __ldg(reinterpret_cast<const uint4*>(yh_in + (size_t)gw * HID) + li);
    acc8(vs, 1.0f, acc);
    float part = 0.f;
#pragma unroll
    for (int c = 0; c < 8; c++) {
        float a = fmaxf(fmaf(acc[c], dis, bs[li * 8 + c]), 0.f);
        part = fmaf(a, W4s[li * 8 + c], part);
    }
    part += __shfl_xor_sync(0xffffffffu, part, 1);
    if (lane == 0) g_y4h[gw] = part * dis;
}

// layer-4 pull + fused global mean pool
__global__ void __launch_bounds__(256, 6)
k_pull1(const float* __restrict__ b4, float* __restrict__ out) {
    int gw = (blockIdx.x * blockDim.x + threadIdx.x) >> 5;
    int lane = threadIdx.x & 31;
    int wid = threadIdx.x >> 5;
    __shared__ float sbuf[8];

    float v = 0.f;
    if (gw < N_NODES) {
        int beg = g_off[gw], end = g_off[gw + 1];
        float acc = 0.f;
        for (int e = beg + lane; e < end; e += 32) {
            unsigned int c = __ldg(&g_csru[e]);
            acc = fmaf(__ldg(&g_y4h[c & SRC_MASK]),
                       (float)(c >> 17) * (1.0f / WQ_SCALE), acc);
        }
#pragma unroll
        for (int o = 16; o > 0; o >>= 1)
            acc += __shfl_xor_sync(0xffffffffu, acc, o);
        float agg4 = (acc + g_y4h[gw]) * g_dis[gw];
        v = fmaxf(agg4 + b4[0], 0.f) * (1.0f / (float)N_NODES);
    }
    if (lane == 0) sbuf[wid] = v;
    __syncthreads();
    if (wid == 0) {
        v = (lane < (int)(blockDim.x >> 5)) ? sbuf[lane] : 0.f;
#pragma unroll
        for (int o = 4; o > 0; o >>= 1) v += __shfl_down_sync(0xffffffffu, v, o);
        if (lane == 0) atomicAdd(out, v);
    }
}

// ---------------- launch ------------------------------------------------------

extern "C" void kernel_launch(void* const* d_in, const int* in_sizes, int n_in,
                              void* d_out, int out_size) {
    const float* vf    = (const float*)d_in[0];
    const void*  edges = d_in[1];
    const float* w     = (const float*)d_in[2];
    const float* W1    = (const float*)d_in[3];
    const float* b1    = (const float*)d_in[4];
    const float* W2    = (const float*)d_in[5];
    const float* b2    = (const float*)d_in[6];
    const float* W3    = (const float*)d_in[7];
    const float* b3    = (const float*)d_in[8];
    const float* W4    = (const float*)d_in[9];
    const float* b4    = (const float*)d_in[10];
    float*       out   = (float*)d_out;

    const int NB_N = (N_NODES + 255) / 256;
    const int NB_E = (N_EDGES + 255) / 256;
    const int NB_W = (N_NODES * 32 + 255) / 256;   // warp-per-node grids

    // ---- CSR build (fill is atomic-free via rank capture) ----
    k_init<<<NB_N, 256>>>((const long long*)edges);
    k_edge_pre<<<NB_E, 256>>>(edges, w);
    k_scan1<<<NB_SCAN, SCAN_BLK>>>();
    k_scan2<<<1, 128>>>();
    k_scan3<<<NB_N, 256>>>();
    k_csr_fill<<<NB_E, 256>>>(edges, w);

    // ---- 4 GCN layers (fused pull + transform, ping-pong A/B) ----
    k_t1<<<NB_N, 256>>>(vf, W1);                 // -> A
    k_pull_mid<<<NB_W, 256>>>(1, W2, b1);        // A -> B
    k_pull_mid<<<NB_W, 256>>>(0, W3, b2);        // B -> A
    k_pull_last<<<NB_W, 256>>>(W4, b3, out);     // A -> y4h, zero out

    k_pull1<<<NB_W, 256>>>(b4, out);
}